// round 1
// baseline (speedup 1.0000x reference)
#include <cuda_runtime.h>
#include <cuda_bf16.h>

#define L1N 16          // L2+1
#define DIN 1536
#define COUNT 8
#define L3N 64
#define BMAX 16384
#define CTA_SAMPLES 128

// ---- device scratch (static allocs are allowed) ----
__device__ float g_wsum[COUNT * DIN * L1N];   // [b][k][o], o contiguous (16 floats per k)
__device__ float g_bsum[COUNT * L1N];
__device__ float g_w2p[COUNT * L3N * 32];     // W2 padded 30 -> 32
__device__ int   g_cnt[COUNT];
__device__ int   g_cur[COUNT];
__device__ int   g_aoff[COUNT + 1];
__device__ int   g_order[BMAX + COUNT * CTA_SAMPLES];

// ---------------- prep: fold W1+Wf, pad W2, zero counters ----------------
__global__ void k_prep(const float* __restrict__ W1, const float* __restrict__ b1,
                       const float* __restrict__ Wf, const float* __restrict__ bf,
                       const float* __restrict__ W2) {
    int tid = blockIdx.x * blockDim.x + threadIdx.x;
    int stride = gridDim.x * blockDim.x;
    for (int idx = tid; idx < COUNT * DIN * L1N; idx += stride) {
        int b = idx / (DIN * L1N);
        int r = idx - b * (DIN * L1N);
        int k = r >> 4;
        int o = r & 15;
        g_wsum[idx] = W1[(b * L1N + o) * DIN + k] + Wf[o * DIN + k];
    }
    for (int idx = tid; idx < COUNT * L3N * 32; idx += stride) {
        int b = idx >> 11;
        int j = (idx >> 5) & 63;
        int i = idx & 31;
        g_w2p[idx] = (i < 30) ? W2[(b * L3N + j) * 30 + i] : 0.0f;
    }
    for (int idx = tid; idx < COUNT * L1N; idx += stride) {
        int b = idx >> 4, o = idx & 15;
        g_bsum[idx] = b1[b * L1N + o] + bf[o];
    }
    if (tid < COUNT) { g_cnt[tid] = 0; }
}

// ---------------- histogram ----------------
__global__ void k_hist(const int* __restrict__ ls, int n) {
    __shared__ int sc[COUNT];
    int t = threadIdx.x;
    if (t < COUNT) sc[t] = 0;
    __syncthreads();
    int i = blockIdx.x * blockDim.x + t;
    if (i < n) atomicAdd(&sc[ls[i]], 1);
    __syncthreads();
    if (t < COUNT) atomicAdd(&g_cnt[t], sc[t]);
}

// ---------------- scan (pad each bucket to 128) + fill sentinels ----------------
__global__ void k_scan() {
    __shared__ int total_s;
    if (threadIdx.x == 0) {
        int off = 0;
        for (int b = 0; b < COUNT; ++b) {
            g_aoff[b] = off;
            g_cur[b]  = off;
            off += (g_cnt[b] + CTA_SAMPLES - 1) & ~(CTA_SAMPLES - 1);
        }
        g_aoff[COUNT] = off;
        total_s = off;
    }
    __syncthreads();
    int total = total_s;
    for (int i = threadIdx.x; i < total; i += blockDim.x) g_order[i] = -1;
}

// ---------------- scatter ----------------
__global__ void k_scatter(const int* __restrict__ ls, int n) {
    int i = blockIdx.x * blockDim.x + threadIdx.x;
    if (i < n) {
        int b = ls[i];
        int p = atomicAdd(&g_cur[b], 1);
        g_order[p] = i;
    }
}

// ---------------- main fused kernel ----------------
// smem: wsum 24576 f + w2p 2048 f + bsum 16 + b2 64 + wo 64 = 26768 floats
#define SMEM_FLOATS 26768
#define SMEM_BYTES  (SMEM_FLOATS * 4)

__global__ void __launch_bounds__(128, 1) k_main(const float* __restrict__ x,
                                                 const float* __restrict__ b2,
                                                 const float* __restrict__ Wo,
                                                 const float* __restrict__ bo,
                                                 float* __restrict__ out) {
    extern __shared__ float sm[];
    float* ws  = sm;             // [k][16]
    float* w2s = sm + 24576;     // [j][32]
    float* bs  = w2s + 2048;     // 16
    float* b2s = bs + 16;        // 64
    float* wos = b2s + 64;       // 64

    int tid = threadIdx.x;
    int base = blockIdx.x * CTA_SAMPLES;
    if (base >= g_aoff[COUNT]) return;

    int b = 0;
#pragma unroll
    for (int t = 1; t < COUNT; ++t)
        if (base >= g_aoff[t]) b = t;

    // stage weights
    {
        const float4* src = (const float4*)(g_wsum + b * (DIN * L1N));
        float4* dst = (float4*)ws;
        for (int i = tid; i < (DIN * L1N) / 4; i += 128) dst[i] = src[i];
    }
    {
        const float4* src = (const float4*)(g_w2p + b * (L3N * 32));
        float4* dst = (float4*)w2s;
        for (int i = tid; i < (L3N * 32) / 4; i += 128) dst[i] = src[i];
    }
    if (tid < 16) bs[tid] = g_bsum[b * L1N + tid];
    if (tid < 64) b2s[tid] = b2[b * L3N + tid];
    else if (tid < 128) wos[tid - 64] = Wo[b * L3N + (tid - 64)];
    __syncthreads();

    int pos = base + tid;
    int sidx = g_order[pos];
    bool valid = sidx >= 0;
    const float4* xp = (const float4*)(x + (valid ? sidx : 0) * DIN);

    // 16 fp32 accumulators as 8 packed f32x2 pairs
    unsigned long long acc[8];
#pragma unroll
    for (int i = 0; i < 8; ++i) acc[i] = 0ULL;

    // prefetch pipeline: 4 float4 quads in flight (64B/lane ahead)
    float4 buf[4];
#pragma unroll
    for (int j = 0; j < 4; ++j) buf[j] = xp[j];

    const ulonglong2* wp = (const ulonglong2*)ws;  // per k: 4 x ulonglong2 = 16 floats

#pragma unroll 1
    for (int q = 0; q < DIN / 4; q += 4) {
#pragma unroll
        for (int j = 0; j < 4; ++j) {
            float4 cur = buf[j];
            int nq = q + 4 + j;
            if (nq < DIN / 4) buf[j] = xp[nq];
            int k0 = (q + j) * 4;
#pragma unroll
            for (int t = 0; t < 4; ++t) {
                float xv = (t == 0) ? cur.x : (t == 1) ? cur.y : (t == 2) ? cur.z : cur.w;
                unsigned long long xd;
                asm("mov.b64 %0, {%1, %1};" : "=l"(xd) : "f"(xv));
                const ulonglong2* wr = wp + (unsigned)(k0 + t) * 4;
#pragma unroll
                for (int p = 0; p < 4; ++p) {
                    ulonglong2 wv = wr[p];
                    asm("fma.rn.f32x2 %0, %1, %2, %0;"
                        : "+l"(acc[2 * p]) : "l"(xd), "l"(wv.x));
                    asm("fma.rn.f32x2 %0, %1, %2, %0;"
                        : "+l"(acc[2 * p + 1]) : "l"(xd), "l"(wv.y));
                }
            }
        }
    }

    float l1[16];
#pragma unroll
    for (int p = 0; p < 8; ++p) {
        float lo, hi;
        asm("mov.b64 {%0, %1}, %2;" : "=f"(lo), "=f"(hi) : "l"(acc[p]));
        l1[2 * p]     = lo + bs[2 * p];
        l1[2 * p + 1] = hi + bs[2 * p + 1];
    }

    // ---- layer 1 nonlinearity ----
    const float C = 127.0f / 128.0f;
    float lx[32];
#pragma unroll
    for (int i = 0; i < 15; ++i) {
        float v = l1[i];
        float sq = (v * v) * C;
        lx[i]      = fminf(fmaxf(sq, 0.0f), 1.0f);
        lx[15 + i] = fminf(fmaxf(v, 0.0f), 1.0f);
    }
    lx[30] = 0.0f;
    lx[31] = 0.0f;

    // ---- layers 2 + 3 fused ----
    float l3 = 0.0f;
#pragma unroll 4
    for (int j = 0; j < L3N; ++j) {
        float s = b2s[j];
        const float4* wr = (const float4*)(w2s + j * 32);
#pragma unroll
        for (int p = 0; p < 8; ++p) {
            float4 wv = wr[p];
            s = fmaf(lx[4 * p + 0], wv.x, s);
            s = fmaf(lx[4 * p + 1], wv.y, s);
            s = fmaf(lx[4 * p + 2], wv.z, s);
            s = fmaf(lx[4 * p + 3], wv.w, s);
        }
        float s2 = fminf(fmaxf(s, 0.0f), 1.0f);
        l3 = fmaf(s2, wos[j], l3);
    }

    float res = l3 + bo[b] + l1[15];
    if (valid) out[sidx] = res;
}

// ---------------- launch ----------------
extern "C" void kernel_launch(void* const* d_in, const int* in_sizes, int n_in,
                              void* d_out, int out_size) {
    const float* x  = (const float*)d_in[0];
    const int*   ls = (const int*)d_in[1];
    const float* W1 = (const float*)d_in[2];
    const float* b1 = (const float*)d_in[3];
    const float* Wf = (const float*)d_in[4];
    const float* bf = (const float*)d_in[5];
    const float* W2 = (const float*)d_in[6];
    const float* b2 = (const float*)d_in[7];
    const float* Wo = (const float*)d_in[8];
    const float* bo = (const float*)d_in[9];
    float* out = (float*)d_out;
    int n = in_sizes[1];
    if (n > BMAX) n = BMAX;

    cudaFuncSetAttribute(k_main, cudaFuncAttributeMaxDynamicSharedMemorySize, SMEM_BYTES);

    k_prep<<<192, 256>>>(W1, b1, Wf, bf, W2);
    k_hist<<<(n + 255) / 256, 256>>>(ls, n);
    k_scan<<<1, 256>>>();
    k_scatter<<<(n + 255) / 256, 256>>>(ls, n);

    int nblk = (n + CTA_SAMPLES - 1) / CTA_SAMPLES + COUNT;
    k_main<<<nblk, 128, SMEM_BYTES>>>(x, b2, Wo, bo, out);
}